// round 3
// baseline (speedup 1.0000x reference)
#include <cuda_runtime.h>
#include <cuda_bf16.h>

#define B_    8
#define TMAX  256
#define UMAX  128
#define V_    512

#define LOG2E 1.4426950408889634f
#define LN2   0.6931471805599453f
#define NEGF  (-1e30f)

// Guard pads: dp prefetch runs up to ~135 diagonals past the active window in
// both directions; pads make those loads safe (values are select-discarded).
#define GB 17408
#define GA 18432
__device__ float g_blank_pad[GB + B_ * TMAX * (UMAX + 1) + GA]; // log2-domain blank lp
__device__ float g_emit_pad [GB + B_ * TMAX * UMAX       + GA]; // log2-domain emit lp
__device__ float g_lp[B_];                                      // per-batch final (log2)

__device__ __forceinline__ float ex2f(float x) { float r; asm("ex2.approx.ftz.f32 %0,%1;" : "=f"(r) : "f"(x)); return r; }
__device__ __forceinline__ float lg2f(float x) { float r; asm("lg2.approx.ftz.f32 %0,%1;" : "=f"(r) : "f"(x)); return r; }

// ---------------------------------------------------------------------------
// Kernel 1: per-(b,t,u) log-softmax reduced to blank/emit log-probs (log2 dom).
// One warp per 512-float row; rows outside the active region are skipped.
// (Unchanged: measured at 66% DRAM ~= its streaming roofline.)
// ---------------------------------------------------------------------------
__global__ __launch_bounds__(256) void lse_kernel(const float* __restrict__ logits,
                                                  const int*   __restrict__ y,
                                                  const int*   __restrict__ T_len,
                                                  const int*   __restrict__ U_len)
{
    const int ROWS = B_ * TMAX * (UMAX + 1);
    int row  = blockIdx.x * 8 + (threadIdx.x >> 5);
    int lane = threadIdx.x & 31;
    if (row >= ROWS) return;

    int u  = row % (UMAX + 1);
    int bt = row / (UMAX + 1);
    int t  = bt % TMAX;
    int b  = bt / TMAX;
    if (t >= T_len[b] || u > U_len[b]) return;

    const float* rowp = logits + (size_t)row * V_;
    const float4* p   = (const float4*)rowp;

    float4 r0 = p[lane];
    float4 r1 = p[lane + 32];
    float4 r2 = p[lane + 64];
    float4 r3 = p[lane + 96];

    float m = fmaxf(fmaxf(fmaxf(r0.x, r0.y), fmaxf(r0.z, r0.w)),
                    fmaxf(fmaxf(r1.x, r1.y), fmaxf(r1.z, r1.w)));
    m = fmaxf(m, fmaxf(fmaxf(fmaxf(r2.x, r2.y), fmaxf(r2.z, r2.w)),
                       fmaxf(fmaxf(r3.x, r3.y), fmaxf(r3.z, r3.w))));
    #pragma unroll
    for (int o = 16; o > 0; o >>= 1)
        m = fmaxf(m, __shfl_xor_sync(0xffffffffu, m, o));

    float s = __expf(r0.x - m) + __expf(r0.y - m) + __expf(r0.z - m) + __expf(r0.w - m)
            + __expf(r1.x - m) + __expf(r1.y - m) + __expf(r1.z - m) + __expf(r1.w - m)
            + __expf(r2.x - m) + __expf(r2.y - m) + __expf(r2.z - m) + __expf(r2.w - m)
            + __expf(r3.x - m) + __expf(r3.y - m) + __expf(r3.z - m) + __expf(r3.w - m);
    #pragma unroll
    for (int o = 16; o > 0; o >>= 1)
        s += __shfl_xor_sync(0xffffffffu, s, o);

    float lse = m + __logf(s);

    if (lane == 0) {
        g_blank_pad[GB + row] = (r0.x - lse) * LOG2E;
        if (u < UMAX) {
            int yv = y[b * UMAX + u];
            g_emit_pad[GB + (b * TMAX + t) * UMAX + u] = (__ldg(rowp + yv) - lse) * LOG2E;
        }
    }
}

// ---------------------------------------------------------------------------
// Kernel 2: alpha DP, ONE WARP per batch. Lane l owns columns u=4l+1..4l+4.
// Cross-lane dependency = single shfl_up per diagonal (no barriers, no smem).
// logaddexp via 1 ex2 + 1 lg2. Depth-4 rotating register prefetch.
// ---------------------------------------------------------------------------
__global__ __launch_bounds__(32, 1) void dp_kernel(const int* __restrict__ T_len,
                                                   const int* __restrict__ U_len)
{
    const int b = blockIdx.x;
    const int l = threadIdx.x;
    const int T = T_len[b];
    const int U = U_len[b];

    const float* blb = g_blank_pad + GB + b * TMAX * (UMAX + 1);
    const float* emb = g_emit_pad  + GB + b * TMAX * UMAX;

    const int uA = 4 * l + 1;        // columns uA, uA+1, uA+2, uA+3 (covers u=1..128)

    // Load pointers, positioned for diagonal d=1:
    //   blank[(d-u-1)*129 + u],  emit[(d-u)*128 + (u-1)],  u0-chain blank[(d-1)*129]
    const float* pb0 = blb + (0 - uA)     * 129 + uA;
    const float* pb1 = blb + (0 - uA - 1) * 129 + uA + 1;
    const float* pb2 = blb + (0 - uA - 2) * 129 + uA + 2;
    const float* pb3 = blb + (0 - uA - 3) * 129 + uA + 3;
    const float* pe0 = emb + (1 - uA)     * 128 + uA - 1;
    const float* pe1 = emb + (0 - uA)     * 128 + uA;
    const float* pe2 = emb + (-1 - uA)    * 128 + uA + 1;
    const float* pe3 = emb + (-2 - uA)    * 128 + uA + 2;
    const float* pu  = blb;

    // 4 prefetch slots (one diagonal each): 4 blank + 4 emit + 1 u0-broadcast
    float sb[4][4], se[4][4], su[4];
    #pragma unroll
    for (int s = 0; s < 4; ++s) {
        sb[s][0] = __ldg(pb0); pb0 += 129;
        sb[s][1] = __ldg(pb1); pb1 += 129;
        sb[s][2] = __ldg(pb2); pb2 += 129;
        sb[s][3] = __ldg(pb3); pb3 += 129;
        se[s][0] = __ldg(pe0); pe0 += 128;
        se[s][1] = __ldg(pe1); pe1 += 128;
        se[s][2] = __ldg(pe2); pe2 += 128;
        se[s][3] = __ldg(pe3); pe3 += 128;
        su[s]    = __ldg(pu);  pu  += 129;
    }

    float cur0 = NEGF, cur1 = NEGF, cur2 = NEGF, cur3 = NEGF;
    float curU0 = 0.f;               // alpha[.][0] chain; alpha[0][0] = 0

    const int dmax  = (T - 1) + U;
    const int dmaxR = ((dmax + 3) >> 2) << 2;

#define CELL(CUR, LEFT, BLV, EMV, UU, D)                                  \
    {                                                                     \
        const int  t   = (D) - (UU);                                      \
        const bool act = (t >= 0) && (t < T) && ((UU) <= U);              \
        const float x  = (t == 0) ? NEGF : CUR + (BLV);                   \
        const float yv = (LEFT) + (EMV);                                  \
        const float mx = fmaxf(x, yv);                                    \
        const float mn = fminf(x, yv);                                    \
        const float r  = mx + lg2f(1.0f + ex2f(mn - mx));                 \
        CUR = act ? r : CUR;                                              \
    }

#define DP_STEP(S, D)                                                     \
    {                                                                     \
        const float bv0 = sb[S][0], bv1 = sb[S][1], bv2 = sb[S][2], bv3 = sb[S][3]; \
        const float ev0 = se[S][0], ev1 = se[S][1], ev2 = se[S][2], ev3 = se[S][3]; \
        const float uv  = su[S];                                          \
        sb[S][0] = __ldg(pb0); pb0 += 129;                                \
        sb[S][1] = __ldg(pb1); pb1 += 129;                                \
        sb[S][2] = __ldg(pb2); pb2 += 129;                                \
        sb[S][3] = __ldg(pb3); pb3 += 129;                                \
        se[S][0] = __ldg(pe0); pe0 += 128;                                \
        se[S][1] = __ldg(pe1); pe1 += 128;                                \
        se[S][2] = __ldg(pe2); pe2 += 128;                                \
        se[S][3] = __ldg(pe3); pe3 += 128;                                \
        su[S]    = __ldg(pu);  pu  += 129;                                \
        const float lsh  = __shfl_up_sync(0xffffffffu, cur3, 1);          \
        const float lval = (l == 0) ? curU0 : lsh;                        \
        CELL(cur3, cur2, bv3, ev3, uA + 3, D)                             \
        CELL(cur2, cur1, bv2, ev2, uA + 2, D)                             \
        CELL(cur1, cur0, bv1, ev1, uA + 1, D)                             \
        CELL(cur0, lval, bv0, ev0, uA,     D)                             \
        curU0 = ((D) < T) ? curU0 + uv : curU0;                           \
    }

    for (int d = 1; d <= dmaxR; d += 4) {
        DP_STEP(0, d)
        DP_STEP(1, d + 1)
        DP_STEP(2, d + 2)
        DP_STEP(3, d + 3)
    }
#undef DP_STEP
#undef CELL

    // alpha[T-1][U] lives in slot (U-1)&3 of lane (U-1)>>2   (U >= 64 always)
    const int lo = (U - 1) >> 2;
    const int j  = (U - 1) & 3;
    const float c0 = __shfl_sync(0xffffffffu, cur0, lo);
    const float c1 = __shfl_sync(0xffffffffu, cur1, lo);
    const float c2 = __shfl_sync(0xffffffffu, cur2, lo);
    const float c3 = __shfl_sync(0xffffffffu, cur3, lo);
    const float a  = (j == 0) ? c0 : (j == 1) ? c1 : (j == 2) ? c2 : c3;

    if (l == 0)
        g_lp[b] = a + __ldg(blb + (T - 1) * (UMAX + 1) + U);
}

// ---------------------------------------------------------------------------
// Kernel 3: loss = -mean(log_probs), log2 -> natural log.
// ---------------------------------------------------------------------------
__global__ void finalize_kernel(float* __restrict__ out)
{
    float s = (threadIdx.x < B_) ? g_lp[threadIdx.x] : 0.f;
    #pragma unroll
    for (int o = 4; o > 0; o >>= 1)
        s += __shfl_xor_sync(0xffffffffu, s, o);
    if (threadIdx.x == 0) out[0] = -(s * LN2) / (float)B_;
}

extern "C" void kernel_launch(void* const* d_in, const int* in_sizes, int n_in,
                              void* d_out, int out_size)
{
    const float* logits = (const float*)d_in[0];
    const int*   y      = (const int*)  d_in[1];
    const int*   T_len  = (const int*)  d_in[2];
    const int*   U_len  = (const int*)  d_in[3];
    float*       out    = (float*)d_out;

    const int ROWS = B_ * TMAX * (UMAX + 1);
    lse_kernel<<<(ROWS + 7) / 8, 256>>>(logits, y, T_len, U_len);
    dp_kernel<<<B_, 32>>>(T_len, U_len);
    finalize_kernel<<<1, 32>>>(out);
}